// round 1
// baseline (speedup 1.0000x reference)
#include <cuda_runtime.h>
#include <math.h>

#define SS 16
#define NN 4096
#define MM 128
#define DD 128
#define OO 128
#define PAD 129

// scratch (allocation-free requirement -> device globals)
__device__ float g_w[SS*OO*DD];      // sampled weights w[s][o][d]
__device__ float g_klso[SS*OO];      // per-(s,o) kl contribution

struct K1Smem {
    float A[DD*PAD];     // q_prec -> Lc (+ mirrored Lc^T in upper) -> Linv (lower)
    float C[DD*PAD];     // q_cov -> Lcov
    float P[32*PAD];     // phiU chunk (32 rows of M)
    float lp[MM];        // exp(logprec[o])
    float lpm[MM];       // lp * mu
    float utlv[DD];
    float dinv[DD];
    float qmu[DD];
    float epsv[DD];
    float red[DD];
};

__device__ __forceinline__ void chol_sym_inplace(float* A, int tid, int ty, int tx) {
    // In-place Cholesky on full symmetric 128x128 (stride PAD).
    // Maintains symmetry: after completion lower(+diag) = Lc, upper = Lc^T.
    for (int j = 0; j < DD; j++) {
        if (tid == 0) A[j*PAD + j] = sqrtf(A[j*PAD + j]);
        __syncthreads();
        float inv = 1.0f / A[j*PAD + j];
        for (int i = j + 1 + tid; i < DD; i += 256) {
            float v = A[i*PAD + j] * inv;
            A[i*PAD + j] = v;
            A[j*PAD + i] = v;   // mirror
        }
        __syncthreads();
        // trailing full-square rank-1 update (keeps symmetry)
        for (int i = j + 1 + ty; i < DD; i += 16) {
            float aij = A[i*PAD + j];
            for (int k = j + 1 + tx; k < DD; k += 16)
                A[i*PAD + k] -= aij * A[k*PAD + j];
        }
        __syncthreads();
    }
}

__global__ __launch_bounds__(256, 1)
void k1_factor(const float* __restrict__ U,
               const float* __restrict__ pmu,
               const float* __restrict__ plogprec,
               const float* __restrict__ eps) {
    extern __shared__ unsigned char smem_raw[];
    K1Smem& sm = *reinterpret_cast<K1Smem*>(smem_raw);

    const int so = blockIdx.x;
    const int s = so >> 7;
    const int o = so & 127;
    const int tid = threadIdx.x;
    const int ty = tid >> 4, tx = tid & 15;

    if (tid < 128) {
        float l = expf(plogprec[o*MM + tid]);
        sm.lp[tid]  = l;
        sm.lpm[tid] = l * pmu[o*MM + tid];
        sm.epsv[tid] = eps[(s*OO + o)*DD + tid];
        sm.utlv[tid] = 0.0f;
    }

    // ---- Gram: A = phiU^T diag(lp) phiU + I ; utlv = phiU^T (lp*mu) ----
    float acc[8][8];
#pragma unroll
    for (int a = 0; a < 8; a++)
#pragma unroll
        for (int b = 0; b < 8; b++) acc[a][b] = 0.0f;

    for (int mb = 0; mb < MM; mb += 32) {
        __syncthreads();
        for (int idx = tid; idx < 32*DD; idx += 256) {
            int mm = idx >> 7, dd = idx & 127;
            float u = U[(s*MM + mb + mm)*DD + dd];
            sm.P[mm*PAD + dd] = u > 0.0f ? u : 0.0f;
        }
        __syncthreads();
        if (tid < 128) {
            float a = 0.0f;
#pragma unroll 8
            for (int mm = 0; mm < 32; mm++)
                a += sm.lpm[mb + mm] * sm.P[mm*PAD + tid];
            sm.utlv[tid] += a;
        }
        for (int mm = 0; mm < 32; mm++) {
            float wgt = sm.lp[mb + mm];
            float pi[8], pj[8];
#pragma unroll
            for (int a = 0; a < 8; a++) {
                pi[a] = wgt * sm.P[mm*PAD + ty + 16*a];
                pj[a] = sm.P[mm*PAD + tx + 16*a];
            }
#pragma unroll
            for (int a = 0; a < 8; a++)
#pragma unroll
                for (int b = 0; b < 8; b++)
                    acc[a][b] += pi[a] * pj[b];
        }
    }
    __syncthreads();
#pragma unroll
    for (int a = 0; a < 8; a++)
#pragma unroll
        for (int b = 0; b < 8; b++) {
            int i = ty + 16*a, j = tx + 16*b;
            sm.A[i*PAD + j] = acc[a][b] + (i == j ? 1.0f : 0.0f);
        }
    __syncthreads();

    // ---- Lc = chol(A)  (lower = Lc, upper = Lc^T) ----
    chol_sym_inplace(sm.A, tid, ty, tx);

    // ---- X = Lc^{-1} in-place in lower triangle, reading Lc^T from upper ----
    if (tid < DD) sm.dinv[tid] = 1.0f / sm.A[tid*PAD + tid];
    __syncthreads();
    for (int idx = tid; idx < DD*DD; idx += 256) {
        int i = idx >> 7, j = idx & 127;
        if (i > j)      sm.A[i*PAD + j] = 0.0f;
        else if (i == j) sm.A[i*PAD + i] = 1.0f;
    }
    __syncthreads();
    for (int i = 0; i < DD; i++) {
        float di = sm.dinv[i];
        for (int j = tid; j <= i; j += 256) sm.A[i*PAD + j] *= di;
        __syncthreads();
        for (int r = i + 1 + ty; r < DD; r += 16) {
            float lcri = sm.A[i*PAD + r];   // Lc[r][i] from upper mirror
            for (int j = tx; j <= i; j += 16)
                sm.A[r*PAD + j] -= lcri * sm.A[i*PAD + j];
        }
        __syncthreads();
    }
    // zero strict upper so X^T X can loop unconditionally
    for (int idx = tid; idx < DD*DD; idx += 256) {
        int i = idx >> 7, j = idx & 127;
        if (j > i) sm.A[i*PAD + j] = 0.0f;
    }
    __syncthreads();

    // ---- q_cov: C = X^T X ----
#pragma unroll
    for (int a = 0; a < 8; a++)
#pragma unroll
        for (int b = 0; b < 8; b++) acc[a][b] = 0.0f;
    for (int k = 0; k < DD; k++) {
        float xi[8], xj[8];
#pragma unroll
        for (int a = 0; a < 8; a++) {
            xi[a] = sm.A[k*PAD + ty + 16*a];
            xj[a] = sm.A[k*PAD + tx + 16*a];
        }
#pragma unroll
        for (int a = 0; a < 8; a++)
#pragma unroll
            for (int b = 0; b < 8; b++)
                acc[a][b] += xi[a] * xj[b];
    }
#pragma unroll
    for (int a = 0; a < 8; a++)
#pragma unroll
        for (int b = 0; b < 8; b++)
            sm.C[(ty + 16*a)*PAD + tx + 16*b] = acc[a][b];
    __syncthreads();

    // ---- q_mu = q_cov @ utlv ----
    if (tid < DD) {
        float a = 0.0f;
#pragma unroll 8
        for (int e = 0; e < DD; e++) a += sm.C[tid*PAD + e] * sm.utlv[e];
        sm.qmu[tid] = a;
    }
    __syncthreads();

    // tr(q_cov) and |q_mu|^2 (deterministic serial sums by thread 0)
    float tr = 0.0f, musq = 0.0f;
    if (tid == 0) {
        for (int d = 0; d < DD; d++) {
            tr   += sm.C[d*PAD + d];
            musq += sm.qmu[d] * sm.qmu[d];
        }
    }

    // ---- Lcov = chol(q_cov) ----
    chol_sym_inplace(sm.C, tid, ty, tx);

    // ---- logdet + w = q_mu + Lcov @ eps ----
    if (tid < DD) sm.red[tid] = logf(sm.C[tid*PAD + tid]);
    __syncthreads();
    if (tid < DD) {
        float a = sm.qmu[tid];
        for (int e = 0; e <= tid; e++)
            a += sm.C[tid*PAD + e] * sm.epsv[e];
        g_w[(s*OO + o)*DD + tid] = a;
    }
    if (tid == 0) {
        float sumlog = 0.0f;
        for (int d = 0; d < DD; d++) sumlog += sm.red[d];
        g_klso[so] = 0.5f * (tr + musq - (float)DD - 2.0f * sumlog);
    }
}

// ---- k2: F_out[s,n,o] = sum_d relu(F[s,n,d]) w[s,o,d]; same for U_out ----
__global__ __launch_bounds__(256)
void k2_gemm(const float* __restrict__ F, const float* __restrict__ U,
             float* __restrict__ outF, float* __restrict__ outU) {
    __shared__ float At[128][33];
    __shared__ float Bt[128][33];
    const int b = blockIdx.x;
    const int tid = threadIdx.x;
    const int ty = tid >> 4, tx = tid & 15;

    int s;
    const float* Ag;
    float* Cg;
    if (b < SS * (NN/128)) {
        s = b >> 5;
        int nt = b & 31;
        Ag = F + (size_t)(s*NN + nt*128) * DD;
        Cg = outF + (size_t)(s*NN + nt*128) * OO;
    } else {
        s = b - SS * (NN/128);
        Ag = U + (size_t)(s*MM) * DD;
        Cg = outU + (size_t)(s*MM) * OO;
    }
    const float* W = g_w + (size_t)s * OO * DD;

    float acc[8][8];
#pragma unroll
    for (int a = 0; a < 8; a++)
#pragma unroll
        for (int c = 0; c < 8; c++) acc[a][c] = 0.0f;

    for (int kb = 0; kb < DD; kb += 32) {
        __syncthreads();
        for (int idx = tid; idx < 128*32; idx += 256) {
            int r = idx >> 5, c = idx & 31;
            float v = Ag[r*DD + kb + c];
            At[r][c] = v > 0.0f ? v : 0.0f;
            Bt[r][c] = W[r*DD + kb + c];
        }
        __syncthreads();
        for (int kk = 0; kk < 32; kk++) {
            float av[8], bv[8];
#pragma unroll
            for (int a = 0; a < 8; a++) {
                av[a] = At[ty + 16*a][kk];
                bv[a] = Bt[tx + 16*a][kk];
            }
#pragma unroll
            for (int a = 0; a < 8; a++)
#pragma unroll
                for (int c = 0; c < 8; c++)
                    acc[a][c] += av[a] * bv[c];
        }
    }
#pragma unroll
    for (int a = 0; a < 8; a++)
#pragma unroll
        for (int c = 0; c < 8; c++)
            Cg[(ty + 16*a)*OO + tx + 16*c] = acc[a][c];
}

// ---- k3: deterministic KL reduction over o ----
__global__ void k3_kl(float* __restrict__ kl) {
    int s = threadIdx.x;
    if (s < SS) {
        float a = 0.0f;
        for (int o = 0; o < OO; o++) a += g_klso[s*OO + o];
        kl[s] = a;
    }
}

extern "C" void kernel_launch(void* const* d_in, const int* in_sizes, int n_in,
                              void* d_out, int out_size) {
    const float* F        = (const float*)d_in[0];  // [S,N,D]
    const float* U        = (const float*)d_in[1];  // [S,M,D]
    const float* pmu      = (const float*)d_in[2];  // [O,M]
    const float* plogprec = (const float*)d_in[3];  // [O,M]
    const float* eps      = (const float*)d_in[4];  // [S,O,D]

    float* out  = (float*)d_out;
    float* outF = out;                               // [S,N,O]
    float* outU = outF + (size_t)SS*NN*OO;           // [S,M,O]
    float* outK = outU + (size_t)SS*MM*OO;           // [S]

    cudaFuncSetAttribute(k1_factor, cudaFuncAttributeMaxDynamicSharedMemorySize,
                         (int)sizeof(K1Smem));

    k1_factor<<<SS*OO, 256, sizeof(K1Smem)>>>(U, pmu, plogprec, eps);
    k2_gemm<<<SS*(NN/128) + SS, 256>>>(F, U, outF, outU);
    k3_kl<<<1, 32>>>(outK);
}

// round 2
// speedup vs baseline: 1.9016x; 1.9016x over previous
#include <cuda_runtime.h>
#include <math.h>

#define SS 16
#define NN 4096
#define MM 128
#define DD 128
#define OO 128
#define PAD 129

// scratch (allocation-free requirement -> device globals)
__device__ float g_w[SS*OO*DD];      // sampled weights w[s][o][d]
__device__ float g_klso[SS*OO];      // per-(s,o) kl contribution

struct K1Smem {
    float A[DD*PAD];     // q_prec -> raw chol -> (upper: Lc^T mirror, lower: Y=Linv*diag) -> q_cov -> Lcov
    float P[32*PAD];     // phiU chunk (32 rows of M)
    float lp[MM];        // exp(logprec[o])
    float lpm[MM];       // lp * mu
    float utlv[DD];
    float dinv[DD];      // 1/Lc[j][j]
    float qmu[DD];
    float epsv[DD];
    float red[DD];
};

// Deferred-scaling right-looking Cholesky: after this loop, lower+diag of A hold
// the "raw" factors: Lc[i][j] = A[i][j] / sqrt(A[j][j]), Lc[j][j] = sqrt(A[j][j]).
// Only the lower triangle is read/written. ONE sync per column.
__device__ __forceinline__ void chol_deferred(float* A, int ty, int tx) {
    for (int j = 0; j < DD; j++) {
        float inv = 1.0f / A[j*PAD + j];
        float colj[8];
#pragma unroll
        for (int b = 0; b < 8; b++) colj[b] = A[(tx + 16*b)*PAD + j];
        int b_lo = ((j + 1 - tx) + 15) >> 4; if (b_lo < 0) b_lo = 0;
        for (int i = j + 1 + ty; i < DD; i += 16) {
            float coef = A[i*PAD + j] * inv;
            int b_hi = (i - tx) >> 4;
            for (int b = b_lo; b <= b_hi; b++)
                A[i*PAD + tx + 16*b] -= coef * colj[b];
        }
        __syncthreads();
    }
}

__global__ __launch_bounds__(256, 2)
void k1_factor(const float* __restrict__ U,
               const float* __restrict__ pmu,
               const float* __restrict__ plogprec,
               const float* __restrict__ eps) {
    extern __shared__ unsigned char smem_raw[];
    K1Smem& sm = *reinterpret_cast<K1Smem*>(smem_raw);

    const int so = blockIdx.x;
    const int s = so >> 7;
    const int o = so & 127;
    const int tid = threadIdx.x;
    const int ty = tid >> 4, tx = tid & 15;

    if (tid < 128) {
        float l = expf(plogprec[o*MM + tid]);
        sm.lp[tid]  = l;
        sm.lpm[tid] = l * pmu[o*MM + tid];
        sm.epsv[tid] = eps[(s*OO + o)*DD + tid];
        sm.utlv[tid] = 0.0f;
    }

    // ---- Gram: A = phiU^T diag(lp) phiU + I (lower tiles only); utlv ----
    float acc[8][8];
#pragma unroll
    for (int a = 0; a < 8; a++)
#pragma unroll
        for (int b = 0; b < 8; b++) acc[a][b] = 0.0f;

    for (int mb = 0; mb < MM; mb += 32) {
        __syncthreads();
        for (int idx = tid; idx < 32*DD; idx += 256) {
            int mm = idx >> 7, dd = idx & 127;
            float u = U[(s*MM + mb + mm)*DD + dd];
            sm.P[mm*PAD + dd] = u > 0.0f ? u : 0.0f;
        }
        __syncthreads();
        if (tid < 128) {
            float a = 0.0f;
#pragma unroll 8
            for (int mm = 0; mm < 32; mm++)
                a += sm.lpm[mb + mm] * sm.P[mm*PAD + tid];
            sm.utlv[tid] += a;
        }
        for (int mm = 0; mm < 32; mm++) {
            float wgt = sm.lp[mb + mm];
            float pi[8], pj[8];
#pragma unroll
            for (int a = 0; a < 8; a++) pi[a] = sm.P[mm*PAD + ty + 16*a];
#pragma unroll
            for (int b = 0; b < 8; b++) pj[b] = wgt * sm.P[mm*PAD + tx + 16*b];
#pragma unroll
            for (int a = 0; a < 8; a++)
#pragma unroll
                for (int b = 0; b <= a; b++)
                    acc[a][b] += pi[a] * pj[b];
        }
    }
    __syncthreads();
    // store lower tiles (diag-tile upper elems harmlessly written; upper unused)
#pragma unroll
    for (int a = 0; a < 8; a++)
#pragma unroll
        for (int b = 0; b <= a; b++) {
            int i = ty + 16*a, j = tx + 16*b;
            sm.A[i*PAD + j] = acc[a][b] + (i == j ? 1.0f : 0.0f);
        }
    __syncthreads();

    // ---- Lc = chol(A), deferred scaling ----
    chol_deferred(sm.A, ty, tx);

    // finalize: dinv[j] = 1/Lc[j][j]; upper <- Lc^T (strict); lower <- Y init (I)
    if (tid < DD) {
        float raw = sm.A[tid*PAD + tid];
        sm.dinv[tid] = rsqrtf(raw);
        sm.A[tid*PAD + tid] = 1.0f;     // Y diag
    }
    __syncthreads();
    for (int idx = tid; idx < DD*DD; idx += 256) {
        int i = idx >> 7, j = idx & 127;
        if (j < i) {
            float l = sm.A[i*PAD + j] * sm.dinv[j];  // Lc[i][j]
            sm.A[j*PAD + i] = l;                     // mirror -> upper
            sm.A[i*PAD + j] = 0.0f;                  // Y strict lower init
        }
    }
    __syncthreads();

    // ---- forward substitution: Y (lower) with X = diag(dinv) applied lazily ----
    // X = Lc^{-1}; X[i][j] = Y[i][j] * dinv[i]. One sync per row.
    for (int i = 0; i < DD; i++) {
        float dv = sm.dinv[i];
        int b_hi = (i - tx) >> 4;       // j = tx+16b <= i
        float rowi[8];
        for (int b = 0; b <= b_hi; b++) rowi[b] = sm.A[i*PAD + tx + 16*b] * dv;
        for (int r = i + 1 + ty; r < DD; r += 16) {
            float c = sm.A[i*PAD + r];  // Lc[r][i] from upper mirror
            for (int b = 0; b <= b_hi; b++)
                sm.A[r*PAD + tx + 16*b] -= c * rowi[b];
        }
        __syncthreads();
    }

    // zero strict upper (was mirror) so X^T X loop is unconditional
    for (int idx = tid; idx < DD*DD; idx += 256) {
        int i = idx >> 7, j = idx & 127;
        if (j > i) sm.A[i*PAD + j] = 0.0f;
    }
    __syncthreads();

    // ---- q_cov = X^T X = sum_k dinv[k]^2 * Y[k][:]^T Y[k][:]  (registers) ----
#pragma unroll
    for (int a = 0; a < 8; a++)
#pragma unroll
        for (int b = 0; b < 8; b++) acc[a][b] = 0.0f;
    for (int k = 0; k < DD; k++) {
        float dk = sm.dinv[k];
        float d2 = dk * dk;
        float xi[8], xj[8];
#pragma unroll
        for (int a = 0; a < 8; a++) xi[a] = d2 * sm.A[k*PAD + ty + 16*a];
#pragma unroll
        for (int b = 0; b < 8; b++) xj[b] = sm.A[k*PAD + tx + 16*b];
#pragma unroll
        for (int a = 0; a < 8; a++)
#pragma unroll
            for (int b = 0; b <= a; b++)
                acc[a][b] += xi[a] * xj[b];
    }
    __syncthreads();   // all X reads done before overwrite
    // store q_cov (full square via mirrored stores)
#pragma unroll
    for (int a = 0; a < 8; a++)
#pragma unroll
        for (int b = 0; b <= a; b++) {
            int i = ty + 16*a, j = tx + 16*b;
            sm.A[i*PAD + j] = acc[a][b];
            if (b < a) sm.A[j*PAD + i] = acc[a][b];
        }
    __syncthreads();

    // ---- q_mu = q_cov @ utlv ----
    if (tid < DD) {
        float a = 0.0f;
#pragma unroll 8
        for (int e = 0; e < DD; e++) a += sm.A[tid*PAD + e] * sm.utlv[e];
        sm.qmu[tid] = a;
    }
    __syncthreads();

    // tr(q_cov) + |q_mu|^2 partials
    if (tid < DD) sm.red[tid] = sm.A[tid*PAD + tid] + sm.qmu[tid]*sm.qmu[tid];
    __syncthreads();
    float trmu = 0.0f;
    if (tid == 0)
        for (int d = 0; d < DD; d++) trmu += sm.red[d];
    // (no sync needed: chol step j=0 doesn't touch col 0 / diag0 / red)

    // ---- Lcov = chol(q_cov), deferred ----
    chol_deferred(sm.A, ty, tx);

    // finalize: diag = sqrt, red = 0.5*log(rawdiag), scale strict lower
    if (tid < DD) {
        float raw = sm.A[tid*PAD + tid];
        sm.red[tid] = 0.5f * logf(raw);
        float rs = rsqrtf(raw);
        sm.dinv[tid] = rs;
        sm.A[tid*PAD + tid] = raw * rs;   // sqrt(raw)
    }
    __syncthreads();
    for (int idx = tid; idx < DD*DD; idx += 256) {
        int i = idx >> 7, j = idx & 127;
        if (j < i) sm.A[i*PAD + j] *= sm.dinv[j];
    }
    __syncthreads();

    // ---- w = q_mu + Lcov @ eps ; KL ----
    if (tid < DD) {
        float a = sm.qmu[tid];
        for (int e = 0; e <= tid; e++)
            a += sm.A[tid*PAD + e] * sm.epsv[e];
        g_w[(s*OO + o)*DD + tid] = a;
    }
    if (tid == 0) {
        float sumlog = 0.0f;
        for (int d = 0; d < DD; d++) sumlog += sm.red[d];
        g_klso[so] = 0.5f * (trmu - (float)DD) - sumlog;
    }
}

// ---- k2: F_out[s,n,o] = sum_d relu(F[s,n,d]) w[s,o,d]; same for U_out ----
__global__ __launch_bounds__(256)
void k2_gemm(const float* __restrict__ F, const float* __restrict__ U,
             float* __restrict__ outF, float* __restrict__ outU) {
    __shared__ float At[128][33];
    __shared__ float Bt[128][33];
    const int b = blockIdx.x;
    const int tid = threadIdx.x;
    const int ty = tid >> 4, tx = tid & 15;

    int s;
    const float* Ag;
    float* Cg;
    if (b < SS * (NN/128)) {
        s = b >> 5;
        int nt = b & 31;
        Ag = F + (size_t)(s*NN + nt*128) * DD;
        Cg = outF + (size_t)(s*NN + nt*128) * OO;
    } else {
        s = b - SS * (NN/128);
        Ag = U + (size_t)(s*MM) * DD;
        Cg = outU + (size_t)(s*MM) * OO;
    }
    const float* W = g_w + (size_t)s * OO * DD;

    float acc[8][8];
#pragma unroll
    for (int a = 0; a < 8; a++)
#pragma unroll
        for (int c = 0; c < 8; c++) acc[a][c] = 0.0f;

    for (int kb = 0; kb < DD; kb += 32) {
        __syncthreads();
        for (int idx = tid; idx < 128*32; idx += 256) {
            int r = idx >> 5, c = idx & 31;
            float v = Ag[r*DD + kb + c];
            At[r][c] = v > 0.0f ? v : 0.0f;
            Bt[r][c] = W[r*DD + kb + c];
        }
        __syncthreads();
        for (int kk = 0; kk < 32; kk++) {
            float av[8], bv[8];
#pragma unroll
            for (int a = 0; a < 8; a++) {
                av[a] = At[ty + 16*a][kk];
                bv[a] = Bt[tx + 16*a][kk];
            }
#pragma unroll
            for (int a = 0; a < 8; a++)
#pragma unroll
                for (int c = 0; c < 8; c++)
                    acc[a][c] += av[a] * bv[c];
        }
    }
#pragma unroll
    for (int a = 0; a < 8; a++)
#pragma unroll
        for (int c = 0; c < 8; c++)
            Cg[(ty + 16*a)*OO + tx + 16*c] = acc[a][c];
}

// ---- k3: deterministic KL reduction over o ----
__global__ void k3_kl(float* __restrict__ kl) {
    int s = threadIdx.x;
    if (s < SS) {
        float a = 0.0f;
        for (int o = 0; o < OO; o++) a += g_klso[s*OO + o];
        kl[s] = a;
    }
}

extern "C" void kernel_launch(void* const* d_in, const int* in_sizes, int n_in,
                              void* d_out, int out_size) {
    const float* F        = (const float*)d_in[0];  // [S,N,D]
    const float* U        = (const float*)d_in[1];  // [S,M,D]
    const float* pmu      = (const float*)d_in[2];  // [O,M]
    const float* plogprec = (const float*)d_in[3];  // [O,M]
    const float* eps      = (const float*)d_in[4];  // [S,O,D]

    float* out  = (float*)d_out;
    float* outF = out;                               // [S,N,O]
    float* outU = outF + (size_t)SS*NN*OO;           // [S,M,O]
    float* outK = outU + (size_t)SS*MM*OO;           // [S]

    cudaFuncSetAttribute(k1_factor, cudaFuncAttributeMaxDynamicSharedMemorySize,
                         (int)sizeof(K1Smem));

    k1_factor<<<SS*OO, 256, sizeof(K1Smem)>>>(U, pmu, plogprec, eps);
    k2_gemm<<<SS*(NN/128) + SS, 256>>>(F, U, outF, outU);
    k3_kl<<<1, 32>>>(outK);
}

// round 3
// speedup vs baseline: 7.6796x; 4.0384x over previous
#include <cuda_runtime.h>
#include <math.h>

#define SS 16
#define NN 4096
#define MM 128
#define DD 128
#define OO 128
#define PAD 129

__device__ float g_w[SS*OO*DD];
__device__ float g_klso[SS*OO];

struct K1Smem {
    float A[DD*PAD];     // Gram -> L -> X=L^{-1} -> q_cov -> Lcov
    float P[32*PAD];     // phiU staging; reused as trisolve scratch (9*272 floats)
    float lp[MM];
    float lpm[MM];
    float utlv[DD];
    float dinv[DD];      // 1/L[j][j]
    float qmu[DD];
    float epsv[DD];
    float red[DD];
};

// 16x16 Cholesky of diag block by lanes 0..15 of the calling warp.
// A points at block (row stride PAD). dinv[j] receives 1/L[j][j].
__device__ __forceinline__ void chol16_warp(float* A, float* dinv) {
    const int lane = threadIdx.x & 31;
    if (lane < 16) {
        float row[16];
#pragma unroll
        for (int k = 0; k < 16; k++) row[k] = A[lane*PAD + k];
#pragma unroll
        for (int j = 0; j < 16; j++) {
            float raw = __shfl_sync(0xFFFFu, row[j], j);
            float s = rsqrtf(raw);
            if (lane == j) dinv[j] = s;
            row[j] *= s;                 // L[i][j] (lane i>j); lane j: sqrt(raw)
#pragma unroll
            for (int k = j + 1; k < 16; k++) {
                float lkj = __shfl_sync(0xFFFFu, row[j], k);
                row[k] -= row[j] * lkj;  // unconditional; upper lanes produce dead garbage
            }
        }
#pragma unroll
        for (int k = 0; k < 16; k++) A[lane*PAD + k] = row[k];
    }
    __syncwarp();
}

// Blocked in-place Cholesky of 128x128 SPD (lower triangle valid on entry).
// On exit lower+diag hold L (true scaling); dinv[j] = 1/L[j][j]. Upper = garbage.
__device__ __noinline__ void chol_blocked(float* A, float* dinv, int tid) {
    const int warp = tid >> 5;
    const int ty = tid >> 4, tx = tid & 15;
#pragma unroll
    for (int jb = 0; jb < 8; jb++) {
        if (warp == 0) chol16_warp(A + (jb*16)*PAD + jb*16, dinv + jb*16);
        __syncthreads();
        // panel: rows below diag block solve v * L_d^T = a
        const int nrows = 112 - jb*16;
        if (tid < nrows) {
            const int i = jb*16 + 16 + tid;
            const float* Ld = A + (jb*16)*PAD + jb*16;
            float* Ai = A + i*PAD + jb*16;
            float v[16];
#pragma unroll
            for (int j = 0; j < 16; j++) {
                float t = Ai[j];
#pragma unroll
                for (int k = 0; k < j; k++) t -= v[k] * Ld[j*PAD + k];
                v[j] = t * dinv[jb*16 + j];
            }
#pragma unroll
            for (int j = 0; j < 16; j++) Ai[j] = v[j];
        }
        __syncthreads();
        // trailing syrk: tiles (a,b), jb<b<=a<8, branch-free unrolled
        if (jb < 7) {
            float tacc[8][8];
#pragma unroll
            for (int a = jb+1; a < 8; a++)
#pragma unroll
                for (int b = jb+1; b <= a; b++) tacc[a][b] = 0.0f;
            float pa[8], pb[8];
#pragma unroll
            for (int k = 0; k < 16; k++) {
#pragma unroll
                for (int a = jb+1; a < 8; a++) pa[a] = A[(ty + 16*a)*PAD + jb*16 + k];
#pragma unroll
                for (int b = jb+1; b < 8; b++) pb[b] = A[(tx + 16*b)*PAD + jb*16 + k];
#pragma unroll
                for (int a = jb+1; a < 8; a++)
#pragma unroll
                    for (int b = jb+1; b <= a; b++) tacc[a][b] += pa[a] * pb[b];
            }
#pragma unroll
            for (int a = jb+1; a < 8; a++)
#pragma unroll
                for (int b = jb+1; b <= a; b++)
                    A[(ty + 16*a)*PAD + tx + 16*b] -= tacc[a][b];
            __syncthreads();
        }
    }
}

// Blocked X = L^{-1} in place (lower triangle; diag blocks become Dinv blocks,
// zero-padded above their diagonal). dinv[] from chol_blocked. scratch: 9*272 floats.
__device__ __noinline__ void trsm_blocked(float* A, const float* dinv,
                                          float* scratch, int tid) {
    const int warp = tid >> 5;
    const int lane = tid & 31;
    const int c = lane & 15, rh = lane >> 4;
#pragma unroll
    for (int ib = 0; ib < 8; ib++) {
        // warp 7, lanes<16: Dinv = inv(L[ib][ib]) column-parallel fwd-subst
        if (warp == 7 && lane < 16) {
            const float* Ld = A + (ib*16)*PAD + ib*16;
            float x[16];
#pragma unroll
            for (int r = 0; r < 16; r++) {
                float t = (r == c) ? 1.0f : 0.0f;
#pragma unroll
                for (int k = 0; k < r; k++) t -= Ld[r*PAD + k] * x[k];
                x[r] = t * dinv[ib*16 + r];   // zero for r<c automatically
            }
#pragma unroll
            for (int r = 0; r < 16; r++) scratch[8*272 + r*17 + c] = x[r];
        }
        // warps 0..ib-1: T = -sum_kb L[ib][kb] X[kb][jb]
        float acc[8];
        if (warp < ib) {
#pragma unroll
            for (int q = 0; q < 8; q++) acc[q] = 0.0f;
            for (int kb = warp; kb < ib; kb++) {
#pragma unroll
                for (int k = 0; k < 16; k++) {
                    float xv = A[(kb*16 + k)*PAD + warp*16 + c];
#pragma unroll
                    for (int q = 0; q < 8; q++)
                        acc[q] -= A[(ib*16 + rh*8 + q)*PAD + kb*16 + k] * xv;
                }
            }
#pragma unroll
            for (int q = 0; q < 8; q++)
                scratch[warp*272 + (rh*8 + q)*17 + c] = acc[q];
        }
        __syncthreads();
        // X[ib][jb] = Dinv @ T ; X[ib][ib] = Dinv
        if (warp < ib) {
            const float* Dv = scratch + 8*272;
            const float* T  = scratch + warp*272;
#pragma unroll
            for (int q = 0; q < 8; q++) {
                const int r = rh*8 + q;
                float t = 0.0f;
#pragma unroll
                for (int k = 0; k < 16; k++) t += Dv[r*17 + k] * T[k*17 + c];
                A[(ib*16 + r)*PAD + warp*16 + c] = t;
            }
        }
        if (warp == 7 && lane < 16) {
            const float* Dv = scratch + 8*272;
#pragma unroll
            for (int r = 0; r < 16; r++)
                A[(ib*16 + r)*PAD + ib*16 + c] = Dv[r*17 + c];
        }
        __syncthreads();
    }
}

__global__ __launch_bounds__(256, 2)
void k1_factor(const float* __restrict__ U,
               const float* __restrict__ pmu,
               const float* __restrict__ plogprec,
               const float* __restrict__ eps) {
    extern __shared__ unsigned char smem_raw[];
    K1Smem& sm = *reinterpret_cast<K1Smem*>(smem_raw);

    const int so = blockIdx.x;
    const int s = so >> 7;
    const int o = so & 127;
    const int tid = threadIdx.x;
    const int ty = tid >> 4, tx = tid & 15;

    if (tid < 128) {
        float l = expf(plogprec[o*MM + tid]);
        sm.lp[tid]   = l;
        sm.lpm[tid]  = l * pmu[o*MM + tid];
        sm.epsv[tid] = eps[(s*OO + o)*DD + tid];
        sm.utlv[tid] = 0.0f;
    }

    // ---- Gram: A = phiU^T diag(lp) phiU + I (lower tiles + full diag tiles) ----
    float acc[8][8];
#pragma unroll
    for (int a = 0; a < 8; a++)
#pragma unroll
        for (int b = 0; b < 8; b++) acc[a][b] = 0.0f;

    for (int mb = 0; mb < MM; mb += 32) {
        __syncthreads();
        for (int idx = tid; idx < 32*DD; idx += 256) {
            int mm = idx >> 7, dd = idx & 127;
            float u = U[(s*MM + mb + mm)*DD + dd];
            sm.P[mm*PAD + dd] = u > 0.0f ? u : 0.0f;
        }
        __syncthreads();
        if (tid < 128) {
            float a = 0.0f;
#pragma unroll 8
            for (int mm = 0; mm < 32; mm++)
                a += sm.lpm[mb + mm] * sm.P[mm*PAD + tid];
            sm.utlv[tid] += a;
        }
        for (int mm = 0; mm < 32; mm++) {
            float wgt = sm.lp[mb + mm];
            float pi[8], pj[8];
#pragma unroll
            for (int a = 0; a < 8; a++) pi[a] = sm.P[mm*PAD + ty + 16*a];
#pragma unroll
            for (int b = 0; b < 8; b++) pj[b] = wgt * sm.P[mm*PAD + tx + 16*b];
#pragma unroll
            for (int a = 0; a < 8; a++)
#pragma unroll
                for (int b = 0; b <= a; b++)
                    acc[a][b] += pi[a] * pj[b];
        }
    }
    __syncthreads();
#pragma unroll
    for (int a = 0; a < 8; a++)
#pragma unroll
        for (int b = 0; b <= a; b++) {
            int i = ty + 16*a, j = tx + 16*b;
            sm.A[i*PAD + j] = acc[a][b] + (i == j ? 1.0f : 0.0f);
        }
    __syncthreads();

    // ---- L = chol(A) (blocked) ----
    chol_blocked(sm.A, sm.dinv, tid);

    // ---- X = L^{-1} (blocked, in place) ----
    trsm_blocked(sm.A, sm.dinv, sm.P, tid);

    // zero strict upper so X^T X can run unconditional k-range
    for (int idx = tid; idx < DD*DD; idx += 256) {
        int i = idx >> 7, j = idx & 127;
        if (j > i) sm.A[i*PAD + j] = 0.0f;
    }
    __syncthreads();

    // ---- q_cov = X^T X (registers, triangular tiles) ----
#pragma unroll
    for (int a = 0; a < 8; a++)
#pragma unroll
        for (int b = 0; b < 8; b++) acc[a][b] = 0.0f;
    for (int k = 0; k < DD; k++) {
        float xi[8], xj[8];
#pragma unroll
        for (int a = 0; a < 8; a++) xi[a] = sm.A[k*PAD + ty + 16*a];
#pragma unroll
        for (int b = 0; b < 8; b++) xj[b] = sm.A[k*PAD + tx + 16*b];
#pragma unroll
        for (int a = 0; a < 8; a++)
#pragma unroll
            for (int b = 0; b <= a; b++)
                acc[a][b] += xi[a] * xj[b];
    }
    __syncthreads();
#pragma unroll
    for (int a = 0; a < 8; a++)
#pragma unroll
        for (int b = 0; b <= a; b++) {
            int i = ty + 16*a, j = tx + 16*b;
            sm.A[i*PAD + j] = acc[a][b];
            if (b < a) sm.A[j*PAD + i] = acc[a][b];
        }
    __syncthreads();

    // ---- q_mu = q_cov @ utlv ----
    if (tid < DD) {
        float a = 0.0f;
#pragma unroll 8
        for (int e = 0; e < DD; e++) a += sm.A[tid*PAD + e] * sm.utlv[e];
        sm.qmu[tid] = a;
    }
    __syncthreads();

    if (tid < DD) sm.red[tid] = sm.A[tid*PAD + tid] + sm.qmu[tid]*sm.qmu[tid];
    __syncthreads();
    float trmu = 0.0f;
    if (tid == 0)
        for (int d = 0; d < DD; d++) trmu += sm.red[d];
    __syncthreads();

    // ---- Lcov = chol(q_cov) (blocked) ----
    chol_blocked(sm.A, sm.dinv, tid);

    if (tid < DD) sm.red[tid] = logf(sm.A[tid*PAD + tid]);
    __syncthreads();

    // ---- w = q_mu + Lcov @ eps ; KL ----
    if (tid < DD) {
        float a = sm.qmu[tid];
        for (int e = 0; e <= tid; e++)
            a += sm.A[tid*PAD + e] * sm.epsv[e];
        g_w[(s*OO + o)*DD + tid] = a;
    }
    if (tid == 0) {
        float sumlog = 0.0f;
        for (int d = 0; d < DD; d++) sumlog += sm.red[d];
        g_klso[so] = 0.5f * (trmu - (float)DD) - sumlog;
    }
}

// ---- k2: F_out / U_out GEMMs ----
__global__ __launch_bounds__(256)
void k2_gemm(const float* __restrict__ F, const float* __restrict__ U,
             float* __restrict__ outF, float* __restrict__ outU) {
    __shared__ float At[128][33];
    __shared__ float Bt[128][33];
    const int b = blockIdx.x;
    const int tid = threadIdx.x;
    const int ty = tid >> 4, tx = tid & 15;

    int s;
    const float* Ag;
    float* Cg;
    if (b < SS * (NN/128)) {
        s = b >> 5;
        int nt = b & 31;
        Ag = F + (size_t)(s*NN + nt*128) * DD;
        Cg = outF + (size_t)(s*NN + nt*128) * OO;
    } else {
        s = b - SS * (NN/128);
        Ag = U + (size_t)(s*MM) * DD;
        Cg = outU + (size_t)(s*MM) * OO;
    }
    const float* W = g_w + (size_t)s * OO * DD;

    float acc[8][8];
#pragma unroll
    for (int a = 0; a < 8; a++)
#pragma unroll
        for (int c = 0; c < 8; c++) acc[a][c] = 0.0f;

    for (int kb = 0; kb < DD; kb += 32) {
        __syncthreads();
        for (int idx = tid; idx < 128*32; idx += 256) {
            int r = idx >> 5, c = idx & 31;
            float v = Ag[r*DD + kb + c];
            At[r][c] = v > 0.0f ? v : 0.0f;
            Bt[r][c] = W[r*DD + kb + c];
        }
        __syncthreads();
        for (int kk = 0; kk < 32; kk++) {
            float av[8], bv[8];
#pragma unroll
            for (int a = 0; a < 8; a++) {
                av[a] = At[ty + 16*a][kk];
                bv[a] = Bt[tx + 16*a][kk];
            }
#pragma unroll
            for (int a = 0; a < 8; a++)
#pragma unroll
                for (int c = 0; c < 8; c++)
                    acc[a][c] += av[a] * bv[c];
        }
    }
#pragma unroll
    for (int a = 0; a < 8; a++)
#pragma unroll
        for (int c = 0; c < 8; c++)
            Cg[(ty + 16*a)*OO + tx + 16*c] = acc[a][c];
}

__global__ void k3_kl(float* __restrict__ kl) {
    int s = threadIdx.x;
    if (s < SS) {
        float a = 0.0f;
        for (int o = 0; o < OO; o++) a += g_klso[s*OO + o];
        kl[s] = a;
    }
}

extern "C" void kernel_launch(void* const* d_in, const int* in_sizes, int n_in,
                              void* d_out, int out_size) {
    const float* F        = (const float*)d_in[0];
    const float* U        = (const float*)d_in[1];
    const float* pmu      = (const float*)d_in[2];
    const float* plogprec = (const float*)d_in[3];
    const float* eps      = (const float*)d_in[4];

    float* out  = (float*)d_out;
    float* outF = out;
    float* outU = outF + (size_t)SS*NN*OO;
    float* outK = outU + (size_t)SS*MM*OO;

    cudaFuncSetAttribute(k1_factor, cudaFuncAttributeMaxDynamicSharedMemorySize,
                         (int)sizeof(K1Smem));

    k1_factor<<<SS*OO, 256, sizeof(K1Smem)>>>(U, pmu, plogprec, eps);
    k2_gemm<<<SS*(NN/128) + SS, 256>>>(F, U, outF, outU);
    k3_kl<<<1, 32>>>(outK);
}

// round 4
// speedup vs baseline: 8.2317x; 1.0719x over previous
#include <cuda_runtime.h>
#include <math.h>

#define SS 16
#define NN 4096
#define MM 128
#define DD 128
#define OO 128
#define PAD 129

__device__ float g_w[SS*OO*DD];
__device__ float g_klso[SS*OO];

struct K1Smem {
    float A[DD*PAD];      // Gram -> L -> X=L^{-1} -> q_cov -> Lcov
    float P[2][32*PAD];   // phiU staging (double buffered); [0] reused as trisolve scratch
    float lp[MM];
    float lpm[MM];
    float utlv[DD];
    float dinv[DD];
    float qmu[DD];
    float epsv[DD];
    float red[DD];
};

// 16x16 Cholesky of diag block by lanes 0..15 of the calling warp.
__device__ __forceinline__ void chol16_warp(float* A, float* dinv) {
    const int lane = threadIdx.x & 31;
    if (lane < 16) {
        float row[16];
#pragma unroll
        for (int k = 0; k < 16; k++) row[k] = A[lane*PAD + k];
#pragma unroll
        for (int j = 0; j < 16; j++) {
            float raw = __shfl_sync(0xFFFFu, row[j], j);
            float s = rsqrtf(raw);
            if (lane == j) dinv[j] = s;
            row[j] *= s;
#pragma unroll
            for (int k = j + 1; k < 16; k++) {
                float lkj = __shfl_sync(0xFFFFu, row[j], k);
                row[k] -= row[j] * lkj;
            }
        }
#pragma unroll
        for (int k = 0; k < 16; k++) A[lane*PAD + k] = row[k];
    }
    __syncwarp();
}

// Blocked in-place Cholesky of 128x128 SPD (lower triangle valid on entry).
__device__ __noinline__ void chol_blocked(float* A, float* dinv, int tid) {
    const int warp = tid >> 5;
    const int ty = tid >> 4, tx = tid & 15;
#pragma unroll
    for (int jb = 0; jb < 8; jb++) {
        if (warp == 0) chol16_warp(A + (jb*16)*PAD + jb*16, dinv + jb*16);
        __syncthreads();
        const int nrows = 112 - jb*16;
        if (tid < nrows) {
            const int i = jb*16 + 16 + tid;
            const float* Ld = A + (jb*16)*PAD + jb*16;
            float* Ai = A + i*PAD + jb*16;
            float v[16];
#pragma unroll
            for (int j = 0; j < 16; j++) {
                float t = Ai[j];
#pragma unroll
                for (int k = 0; k < j; k++) t -= v[k] * Ld[j*PAD + k];
                v[j] = t * dinv[jb*16 + j];
            }
#pragma unroll
            for (int j = 0; j < 16; j++) Ai[j] = v[j];
        }
        __syncthreads();
        if (jb < 7) {
            float tacc[8][8];
#pragma unroll
            for (int a = jb+1; a < 8; a++)
#pragma unroll
                for (int b = jb+1; b <= a; b++) tacc[a][b] = 0.0f;
            float pa[8], pb[8];
#pragma unroll
            for (int k = 0; k < 16; k++) {
#pragma unroll
                for (int a = jb+1; a < 8; a++) pa[a] = A[(ty + 16*a)*PAD + jb*16 + k];
#pragma unroll
                for (int b = jb+1; b < 8; b++) pb[b] = A[(tx + 16*b)*PAD + jb*16 + k];
#pragma unroll
                for (int a = jb+1; a < 8; a++)
#pragma unroll
                    for (int b = jb+1; b <= a; b++) tacc[a][b] += pa[a] * pb[b];
            }
#pragma unroll
            for (int a = jb+1; a < 8; a++)
#pragma unroll
                for (int b = jb+1; b <= a; b++)
                    A[(ty + 16*a)*PAD + tx + 16*b] -= tacc[a][b];
            __syncthreads();
        }
    }
}

// Blocked X = L^{-1} in place. Diag blocks become Dinv blocks, zero-padded
// above their diagonal (so X reads with col<=k within a diag block are exact).
__device__ __noinline__ void trsm_blocked(float* A, const float* dinv,
                                          float* scratch, int tid) {
    const int warp = tid >> 5;
    const int lane = tid & 31;
    const int c = lane & 15, rh = lane >> 4;
#pragma unroll
    for (int ib = 0; ib < 8; ib++) {
        if (warp == 7 && lane < 16) {
            const float* Ld = A + (ib*16)*PAD + ib*16;
            float x[16];
#pragma unroll
            for (int r = 0; r < 16; r++) {
                float t = (r == c) ? 1.0f : 0.0f;
#pragma unroll
                for (int k = 0; k < r; k++) t -= Ld[r*PAD + k] * x[k];
                x[r] = t * dinv[ib*16 + r];
            }
#pragma unroll
            for (int r = 0; r < 16; r++) scratch[8*272 + r*17 + c] = x[r];
        }
        float acc[8];
        if (warp < ib) {
#pragma unroll
            for (int q = 0; q < 8; q++) acc[q] = 0.0f;
            for (int kb = warp; kb < ib; kb++) {
#pragma unroll
                for (int k = 0; k < 16; k++) {
                    float xv = A[(kb*16 + k)*PAD + warp*16 + c];
#pragma unroll
                    for (int q = 0; q < 8; q++)
                        acc[q] -= A[(ib*16 + rh*8 + q)*PAD + kb*16 + k] * xv;
                }
            }
#pragma unroll
            for (int q = 0; q < 8; q++)
                scratch[warp*272 + (rh*8 + q)*17 + c] = acc[q];
        }
        __syncthreads();
        if (warp < ib) {
            const float* Dv = scratch + 8*272;
            const float* T  = scratch + warp*272;
#pragma unroll
            for (int q = 0; q < 8; q++) {
                const int r = rh*8 + q;
                float t = 0.0f;
#pragma unroll
                for (int k = 0; k < 16; k++) t += Dv[r*17 + k] * T[k*17 + c];
                A[(ib*16 + r)*PAD + warp*16 + c] = t;
            }
        }
        if (warp == 7 && lane < 16) {
            const float* Dv = scratch + 8*272;
#pragma unroll
            for (int r = 0; r < 16; r++)
                A[(ib*16 + r)*PAD + ib*16 + c] = Dv[r*17 + c];
        }
        __syncthreads();
    }
}

__global__ __launch_bounds__(256, 2)
void k1_factor(const float* __restrict__ U,
               const float* __restrict__ pmu,
               const float* __restrict__ plogprec,
               const float* __restrict__ eps) {
    extern __shared__ unsigned char smem_raw[];
    K1Smem& sm = *reinterpret_cast<K1Smem*>(smem_raw);

    const int so = blockIdx.x;
    const int s = so >> 7;
    const int o = so & 127;
    const int tid = threadIdx.x;
    const int ty = tid >> 4, tx = tid & 15;

    if (tid < 128) {
        float l = expf(plogprec[o*MM + tid]);
        sm.lp[tid]   = l;
        sm.lpm[tid]  = l * pmu[o*MM + tid];
        sm.epsv[tid] = eps[(s*OO + o)*DD + tid];
        sm.utlv[tid] = 0.0f;
    }

    // ---- Gram: A = phiU^T diag(lp) phiU + I (lower tiles), double-buffered ----
    float acc[8][8];
#pragma unroll
    for (int a = 0; a < 8; a++)
#pragma unroll
        for (int b = 0; b < 8; b++) acc[a][b] = 0.0f;

    // stage chunk 0
    {
        const float4* Ug = (const float4*)(U + (size_t)s*MM*DD);
        for (int idx = tid; idx < 32*32; idx += 256) {
            int mm = idx >> 5, dq = idx & 31;
            float4 u = Ug[mm*32 + dq];
            u.x = fmaxf(u.x, 0.f); u.y = fmaxf(u.y, 0.f);
            u.z = fmaxf(u.z, 0.f); u.w = fmaxf(u.w, 0.f);
            float* dst = &sm.P[0][mm*PAD + 4*dq];
            dst[0]=u.x; dst[1]=u.y; dst[2]=u.z; dst[3]=u.w;
        }
    }
    __syncthreads();

#pragma unroll
    for (int cb = 0; cb < 4; cb++) {
        const int cur = cb & 1;
        if (cb < 3) {
            const float4* Ug = (const float4*)(U + ((size_t)s*MM + (cb+1)*32)*DD);
            float* Pn = sm.P[cur ^ 1];
            for (int idx = tid; idx < 32*32; idx += 256) {
                int mm = idx >> 5, dq = idx & 31;
                float4 u = Ug[mm*32 + dq];
                u.x = fmaxf(u.x, 0.f); u.y = fmaxf(u.y, 0.f);
                u.z = fmaxf(u.z, 0.f); u.w = fmaxf(u.w, 0.f);
                float* dst = &Pn[mm*PAD + 4*dq];
                dst[0]=u.x; dst[1]=u.y; dst[2]=u.z; dst[3]=u.w;
            }
        }
        const float* Pc = sm.P[cur];
        if (tid < 128) {
            float a = 0.0f;
#pragma unroll 8
            for (int mm = 0; mm < 32; mm++)
                a += sm.lpm[cb*32 + mm] * Pc[mm*PAD + tid];
            sm.utlv[tid] += a;
        }
        for (int mm = 0; mm < 32; mm++) {
            float wgt = sm.lp[cb*32 + mm];
            float pi[8], pj[8];
#pragma unroll
            for (int a = 0; a < 8; a++) pi[a] = Pc[mm*PAD + ty + 16*a];
#pragma unroll
            for (int b = 0; b < 8; b++) pj[b] = wgt * Pc[mm*PAD + tx + 16*b];
#pragma unroll
            for (int a = 0; a < 8; a++)
#pragma unroll
                for (int b = 0; b <= a; b++)
                    acc[a][b] += pi[a] * pj[b];
        }
        __syncthreads();
    }
#pragma unroll
    for (int a = 0; a < 8; a++)
#pragma unroll
        for (int b = 0; b <= a; b++) {
            int i = ty + 16*a, j = tx + 16*b;
            sm.A[i*PAD + j] = acc[a][b] + (i == j ? 1.0f : 0.0f);
        }
    __syncthreads();

    // ---- L = chol(A) ----
    chol_blocked(sm.A, sm.dinv, tid);

    // ---- X = L^{-1} ----
    trsm_blocked(sm.A, sm.dinv, sm.P[0], tid);

    // ---- q_cov = X^T X with block-triangular k skipping ----
    // X[k][c] nonzero only for c<=k; col-block b contributes only when kb>=b.
#pragma unroll
    for (int a = 0; a < 8; a++)
#pragma unroll
        for (int b = 0; b < 8; b++) acc[a][b] = 0.0f;
#pragma unroll
    for (int kb = 0; kb < 8; kb++) {
        for (int kk = 0; kk < 16; kk++) {
            const float* Ak = sm.A + (kb*16 + kk)*PAD;
            float xi[8], xj[8];
#pragma unroll
            for (int a = 0; a <= kb; a++) {
                xi[a] = Ak[ty + 16*a];
                xj[a] = Ak[tx + 16*a];
            }
#pragma unroll
            for (int a = 0; a <= kb; a++)
#pragma unroll
                for (int b = 0; b <= a; b++)
                    acc[a][b] += xi[a] * xj[b];
        }
    }
    __syncthreads();
#pragma unroll
    for (int a = 0; a < 8; a++)
#pragma unroll
        for (int b = 0; b <= a; b++) {
            int i = ty + 16*a, j = tx + 16*b;
            sm.A[i*PAD + j] = acc[a][b];
            if (b < a) sm.A[j*PAD + i] = acc[a][b];
        }
    __syncthreads();

    // ---- q_mu = q_cov @ utlv ----
    if (tid < DD) {
        float a = 0.0f;
#pragma unroll 8
        for (int e = 0; e < DD; e++) a += sm.A[tid*PAD + e] * sm.utlv[e];
        sm.qmu[tid] = a;
    }
    __syncthreads();

    if (tid < DD) sm.red[tid] = sm.A[tid*PAD + tid] + sm.qmu[tid]*sm.qmu[tid];
    __syncthreads();
    float trmu = 0.0f;
    if (tid == 0)
        for (int d = 0; d < DD; d++) trmu += sm.red[d];
    __syncthreads();

    // ---- Lcov = chol(q_cov) ----
    chol_blocked(sm.A, sm.dinv, tid);

    if (tid < DD) sm.red[tid] = logf(sm.A[tid*PAD + tid]);
    __syncthreads();

    // ---- w = q_mu + Lcov @ eps ; KL ----
    if (tid < DD) {
        float a = sm.qmu[tid];
        for (int e = 0; e <= tid; e++)
            a += sm.A[tid*PAD + e] * sm.epsv[e];
        g_w[(s*OO + o)*DD + tid] = a;
    }
    if (tid == 0) {
        float sumlog = 0.0f;
        for (int d = 0; d < DD; d++) sumlog += sm.red[d];
        g_klso[so] = 0.5f * (trmu - (float)DD) - sumlog;
    }
}

// ---- k2: F_out / U_out GEMMs, float4-over-k ----
#define KP 36
__global__ __launch_bounds__(256, 2)
void k2_gemm(const float* __restrict__ F, const float* __restrict__ U,
             float* __restrict__ outF, float* __restrict__ outU) {
    __shared__ float At[128*KP];
    __shared__ float Bt[128*KP];
    const int b = blockIdx.x;
    const int tid = threadIdx.x;
    const int ty = tid >> 4, tx = tid & 15;

    int s;
    const float* Ag;
    float* Cg;
    if (b < SS * (NN/128)) {
        s = b >> 5;
        int nt = b & 31;
        Ag = F + (size_t)(s*NN + nt*128) * DD;
        Cg = outF + (size_t)(s*NN + nt*128) * OO;
    } else {
        s = b - SS * (NN/128);
        Ag = U + (size_t)(s*MM) * DD;
        Cg = outU + (size_t)(s*MM) * OO;
    }
    const float* W = g_w + (size_t)s * OO * DD;

    float acc[8][8];
#pragma unroll
    for (int a = 0; a < 8; a++)
#pragma unroll
        for (int c = 0; c < 8; c++) acc[a][c] = 0.0f;

    for (int kb = 0; kb < DD; kb += 32) {
        __syncthreads();
        for (int idx = tid; idx < 128*8; idx += 256) {
            int r = idx >> 3, c4 = idx & 7;
            float4 v = *(const float4*)&Ag[r*DD + kb + 4*c4];
            v.x = fmaxf(v.x, 0.f); v.y = fmaxf(v.y, 0.f);
            v.z = fmaxf(v.z, 0.f); v.w = fmaxf(v.w, 0.f);
            *(float4*)&At[r*KP + 4*c4] = v;
            *(float4*)&Bt[r*KP + 4*c4] = *(const float4*)&W[r*DD + kb + 4*c4];
        }
        __syncthreads();
#pragma unroll
        for (int k4 = 0; k4 < 8; k4++) {
            float4 bv[8];
#pragma unroll
            for (int c = 0; c < 8; c++)
                bv[c] = *(const float4*)&Bt[(tx + 16*c)*KP + 4*k4];
#pragma unroll
            for (int a = 0; a < 8; a++) {
                float4 av = *(const float4*)&At[(ty + 16*a)*KP + 4*k4];
#pragma unroll
                for (int c = 0; c < 8; c++) {
                    acc[a][c] += av.x * bv[c].x;
                    acc[a][c] += av.y * bv[c].y;
                    acc[a][c] += av.z * bv[c].z;
                    acc[a][c] += av.w * bv[c].w;
                }
            }
        }
    }
#pragma unroll
    for (int a = 0; a < 8; a++)
#pragma unroll
        for (int c = 0; c < 8; c++)
            Cg[(ty + 16*a)*OO + tx + 16*c] = acc[a][c];
}

__global__ void k3_kl(float* __restrict__ kl) {
    int s = threadIdx.x;
    if (s < SS) {
        float a = 0.0f;
        for (int o = 0; o < OO; o++) a += g_klso[s*OO + o];
        kl[s] = a;
    }
}

extern "C" void kernel_launch(void* const* d_in, const int* in_sizes, int n_in,
                              void* d_out, int out_size) {
    const float* F        = (const float*)d_in[0];
    const float* U        = (const float*)d_in[1];
    const float* pmu      = (const float*)d_in[2];
    const float* plogprec = (const float*)d_in[3];
    const float* eps      = (const float*)d_in[4];

    float* out  = (float*)d_out;
    float* outF = out;
    float* outU = outF + (size_t)SS*NN*OO;
    float* outK = outU + (size_t)SS*MM*OO;

    cudaFuncSetAttribute(k1_factor, cudaFuncAttributeMaxDynamicSharedMemorySize,
                         (int)sizeof(K1Smem));

    k1_factor<<<SS*OO, 256, sizeof(K1Smem)>>>(U, pmu, plogprec, eps);
    k2_gemm<<<SS*(NN/128) + SS, 256>>>(F, U, outF, outU);
    k3_kl<<<1, 32>>>(outK);
}

// round 5
// speedup vs baseline: 8.2971x; 1.0079x over previous
#include <cuda_runtime.h>
#include <math.h>

#define SS 16
#define NN 4096
#define MM 128
#define DD 128
#define OO 128
#define PAD 129
#define PPAD 132

__device__ float g_w[SS*OO*DD];
__device__ float g_klso[SS*OO];

struct K1Smem {
    float A[DD*PAD];       // Gram -> L -> X=L^{-1} -> q_cov -> Lcov
    float P[2][32*PPAD];   // phiU staging (permuted layout, double buffered); [0] reused as trisolve scratch
    float lp[MM];
    float lpm[MM];
    float utlv[DD];
    float dinv[DD];
    float qmu[DD];
    float epsv[DD];
    float red[DD];
};

// ---- packed f32x2 helpers ----
__device__ __forceinline__ unsigned long long pack2(float lo, float hi) {
    unsigned long long r;
    asm("mov.b64 %0, {%1, %2};" : "=l"(r) : "f"(lo), "f"(hi));
    return r;
}
__device__ __forceinline__ unsigned long long dup2(float v) { return pack2(v, v); }
__device__ __forceinline__ void fma2(unsigned long long& c, unsigned long long a,
                                     unsigned long long b) {
    asm("fma.rn.f32x2 %0, %1, %2, %0;" : "+l"(c) : "l"(a), "l"(b));
}
__device__ __forceinline__ unsigned long long mul2(unsigned long long a,
                                                   unsigned long long b) {
    unsigned long long r;
    asm("mul.rn.f32x2 %0, %1, %2;" : "=l"(r) : "l"(a), "l"(b));
    return r;
}
__device__ __forceinline__ float2 unpack2(unsigned long long v) {
    float2 r;
    asm("mov.b64 {%0, %1}, %2;" : "=f"(r.x), "=f"(r.y) : "l"(v));
    return r;
}

// 16x16 Cholesky of diag block by lanes 0..15, deferred scaling.
__device__ __forceinline__ void chol16_warp(float* A, float* dinv) {
    const int lane = threadIdx.x & 31;
    if (lane < 16) {
        float row[16], rawv[16];
#pragma unroll
        for (int k = 0; k < 16; k++) row[k] = A[lane*PAD + k];
#pragma unroll
        for (int j = 0; j < 16; j++) {
            float raw = __shfl_sync(0xFFFFu, row[j], j);
            rawv[j] = raw;
            float inv = __fdividef(1.0f, raw);
            float tj = row[j] * inv;
#pragma unroll
            for (int k = j + 1; k < 16; k++) {
                float rkj = __shfl_sync(0xFFFFu, row[j], k);
                row[k] = fmaf(-tj, rkj, row[k]);
            }
        }
        float rs[16];
#pragma unroll
        for (int j = 0; j < 16; j++) rs[j] = rsqrtf(rawv[j]);
#pragma unroll
        for (int k = 0; k < 16; k++) {
            float v = row[k];
            if (k < lane)  v = row[k] * rs[k];
            if (k == lane) v = rawv[k] * rs[k];
            A[lane*PAD + k] = v;
        }
        dinv[lane] = rs[lane];
    }
    __syncwarp();
}

// Blocked in-place Cholesky of 128x128 SPD (lower triangle valid on entry).
__device__ __noinline__ void chol_blocked(float* A, float* dinv, int tid) {
    const int warp = tid >> 5;
    const int ty = tid >> 4, tx = tid & 15;
#pragma unroll
    for (int jb = 0; jb < 8; jb++) {
        if (warp == 0) chol16_warp(A + (jb*16)*PAD + jb*16, dinv + jb*16);
        __syncthreads();
        const int nrows = 112 - jb*16;
        if (tid < nrows) {
            const int i = jb*16 + 16 + tid;
            const float* Ld = A + (jb*16)*PAD + jb*16;
            float* Ai = A + i*PAD + jb*16;
            float dv[16], t[16];
#pragma unroll
            for (int j = 0; j < 16; j++) dv[j] = dinv[jb*16 + j];
#pragma unroll
            for (int j = 0; j < 16; j++) t[j] = Ai[j];
#pragma unroll
            for (int j = 0; j < 16; j++) {
                float v = t[j] * dv[j];
                t[j] = v;
#pragma unroll
                for (int k = j + 1; k < 16; k++)
                    t[k] = fmaf(-v, Ld[k*PAD + j], t[k]);
            }
#pragma unroll
            for (int j = 0; j < 16; j++) Ai[j] = t[j];
        }
        __syncthreads();
        if (jb < 7) {
            float tacc[8][8];
#pragma unroll
            for (int a = jb+1; a < 8; a++)
#pragma unroll
                for (int b = jb+1; b <= a; b++) tacc[a][b] = 0.0f;
            float pa[8], pb[8];
#pragma unroll
            for (int k = 0; k < 16; k++) {
#pragma unroll
                for (int a = jb+1; a < 8; a++) pa[a] = A[(ty + 16*a)*PAD + jb*16 + k];
#pragma unroll
                for (int b = jb+1; b < 8; b++) pb[b] = A[(tx + 16*b)*PAD + jb*16 + k];
#pragma unroll
                for (int a = jb+1; a < 8; a++)
#pragma unroll
                    for (int b = jb+1; b <= a; b++) tacc[a][b] += pa[a] * pb[b];
            }
#pragma unroll
            for (int a = jb+1; a < 8; a++)
#pragma unroll
                for (int b = jb+1; b <= a; b++)
                    A[(ty + 16*a)*PAD + tx + 16*b] -= tacc[a][b];
            __syncthreads();
        }
    }
}

// Blocked X = L^{-1} in place. Diag blocks become Dinv blocks, zero-padded above diag.
__device__ __noinline__ void trsm_blocked(float* A, const float* dinv,
                                          float* scratch, int tid) {
    const int warp = tid >> 5;
    const int lane = tid & 31;
    const int c = lane & 15, rh = lane >> 4;
#pragma unroll
    for (int ib = 0; ib < 8; ib++) {
        if (warp == 7 && lane < 16) {
            const float* Ld = A + (ib*16)*PAD + ib*16;
            float dv[16], t[16];
#pragma unroll
            for (int r = 0; r < 16; r++) dv[r] = dinv[ib*16 + r];
#pragma unroll
            for (int r = 0; r < 16; r++) t[r] = (r == c) ? 1.0f : 0.0f;
#pragma unroll
            for (int r = 0; r < 16; r++) {
                float x = t[r] * dv[r];
                t[r] = x;
#pragma unroll
                for (int k = r + 1; k < 16; k++)
                    t[k] = fmaf(-x, Ld[k*PAD + r], t[k]);
            }
#pragma unroll
            for (int r = 0; r < 16; r++) scratch[8*272 + r*17 + c] = t[r];
        }
        float acc[8];
        if (warp < ib) {
#pragma unroll
            for (int q = 0; q < 8; q++) acc[q] = 0.0f;
            for (int kb = warp; kb < ib; kb++) {
#pragma unroll
                for (int k = 0; k < 16; k++) {
                    float xv = A[(kb*16 + k)*PAD + warp*16 + c];
#pragma unroll
                    for (int q = 0; q < 8; q++)
                        acc[q] -= A[(ib*16 + rh*8 + q)*PAD + kb*16 + k] * xv;
                }
            }
#pragma unroll
            for (int q = 0; q < 8; q++)
                scratch[warp*272 + (rh*8 + q)*17 + c] = acc[q];
        }
        __syncthreads();
        if (warp < ib) {
            const float* Dv = scratch + 8*272;
            const float* T  = scratch + warp*272;
#pragma unroll
            for (int q = 0; q < 8; q++) {
                const int r = rh*8 + q;
                float t = 0.0f;
#pragma unroll
                for (int k = 0; k < 16; k++) t += Dv[r*17 + k] * T[k*17 + c];
                A[(ib*16 + r)*PAD + warp*16 + c] = t;
            }
        }
        if (warp == 7 && lane < 16) {
            const float* Dv = scratch + 8*272;
#pragma unroll
            for (int r = 0; r < 16; r++)
                A[(ib*16 + r)*PAD + ib*16 + c] = Dv[r*17 + c];
        }
        __syncthreads();
    }
}

__global__ __launch_bounds__(256, 2)
void k1_factor(const float* __restrict__ U,
               const float* __restrict__ pmu,
               const float* __restrict__ plogprec,
               const float* __restrict__ eps) {
    extern __shared__ unsigned char smem_raw[];
    K1Smem& sm = *reinterpret_cast<K1Smem*>(smem_raw);

    const int so = blockIdx.x;
    const int s = so >> 7;
    const int o = so & 127;
    const int tid = threadIdx.x;
    const int ty = tid >> 4, tx = tid & 15;

    if (tid < 128) {
        float l = expf(plogprec[o*MM + tid]);
        sm.lp[tid]   = l;
        sm.lpm[tid]  = l * pmu[o*MM + tid];
        sm.epsv[tid] = eps[(s*OO + o)*DD + tid];
        sm.utlv[tid] = 0.0f;
    }

    // ---- Gram: A = phiU^T diag(lp) phiU + I (lower tiles), f32x2 packed ----
    // P stored permuted: pos(d) = (d&15)*8 + (d>>4), so pa/pj are vector loads.
    const int OFF0=0, OFF1=1, OFF2=2, OFF3=4, OFF4=6, OFF5=9, OFF6=12, OFF7=16;
    const int OFF[8] = {OFF0,OFF1,OFF2,OFF3,OFF4,OFF5,OFF6,OFF7};
    unsigned long long acc2[20];
#pragma unroll
    for (int q = 0; q < 20; q++) acc2[q] = 0ull;

    // stage chunk 0 (permuted scatter)
    {
        const float4* Ug = (const float4*)(U + (size_t)s*MM*DD);
        for (int idx = tid; idx < 32*32; idx += 256) {
            int mm = idx >> 5, dq = idx & 31;
            float4 u = Ug[mm*32 + dq];
            u.x = fmaxf(u.x, 0.f); u.y = fmaxf(u.y, 0.f);
            u.z = fmaxf(u.z, 0.f); u.w = fmaxf(u.w, 0.f);
            int hi = dq >> 2, lo = (4*dq) & 15;
            float* dst = &sm.P[0][mm*PPAD + hi];
            dst[(lo+0)*8] = u.x; dst[(lo+1)*8] = u.y;
            dst[(lo+2)*8] = u.z; dst[(lo+3)*8] = u.w;
        }
    }
    __syncthreads();

    const int permD = (tid & 15)*8 + (tid >> 4);   // for utlv (tid<128)

#pragma unroll
    for (int cb = 0; cb < 4; cb++) {
        const int cur = cb & 1;
        if (cb < 3) {
            const float4* Ug = (const float4*)(U + ((size_t)s*MM + (cb+1)*32)*DD);
            float* Pn = sm.P[cur ^ 1];
            for (int idx = tid; idx < 32*32; idx += 256) {
                int mm = idx >> 5, dq = idx & 31;
                float4 u = Ug[mm*32 + dq];
                u.x = fmaxf(u.x, 0.f); u.y = fmaxf(u.y, 0.f);
                u.z = fmaxf(u.z, 0.f); u.w = fmaxf(u.w, 0.f);
                int hi = dq >> 2, lo = (4*dq) & 15;
                float* dst = &Pn[mm*PPAD + hi];
                dst[(lo+0)*8] = u.x; dst[(lo+1)*8] = u.y;
                dst[(lo+2)*8] = u.z; dst[(lo+3)*8] = u.w;
            }
        }
        const float* Pc = sm.P[cur];
        if (tid < 128) {
            float a = 0.0f;
#pragma unroll 8
            for (int mm = 0; mm < 32; mm++)
                a += sm.lpm[cb*32 + mm] * Pc[mm*PPAD + permD];
            sm.utlv[tid] += a;
        }
        for (int mm = 0; mm < 32; mm++) {
            const float* Pm = Pc + mm*PPAD;
            float4 qa = *(const float4*)(Pm + ty*8);
            float4 qb = *(const float4*)(Pm + ty*8 + 4);
            float4 ra = *(const float4*)(Pm + tx*8);
            float4 rb = *(const float4*)(Pm + tx*8 + 4);
            unsigned long long w2 = dup2(sm.lp[cb*32 + mm]);
            unsigned long long pj2[4];
            pj2[0] = mul2(pack2(ra.x, ra.y), w2);
            pj2[1] = mul2(pack2(ra.z, ra.w), w2);
            pj2[2] = mul2(pack2(rb.x, rb.y), w2);
            pj2[3] = mul2(pack2(rb.z, rb.w), w2);
            float pav[8] = {qa.x,qa.y,qa.z,qa.w,qb.x,qb.y,qb.z,qb.w};
            unsigned long long pad_[8];
#pragma unroll
            for (int a = 0; a < 8; a++) pad_[a] = dup2(pav[a]);
#pragma unroll
            for (int a = 0; a < 8; a++) {
#pragma unroll
                for (int bp = 0; bp < ((a+2)>>1); bp++)
                    fma2(acc2[OFF[a] + bp], pad_[a], pj2[bp]);
            }
        }
        __syncthreads();
    }
#pragma unroll
    for (int a = 0; a < 8; a++) {
        int i = ty + 16*a;
#pragma unroll
        for (int bp = 0; bp < ((a+2)>>1); bp++) {
            float2 v = unpack2(acc2[OFF[a] + bp]);
            int j0 = tx + 32*bp;
            sm.A[i*PAD + j0] = v.x + (i == j0 ? 1.0f : 0.0f);
            if (2*bp + 1 <= a) {
                int j1 = tx + 16*(2*bp + 1);
                sm.A[i*PAD + j1] = v.y + (i == j1 ? 1.0f : 0.0f);
            }
        }
    }
    __syncthreads();

    // ---- L = chol(A) ----
    chol_blocked(sm.A, sm.dinv, tid);

    // ---- X = L^{-1} ----
    trsm_blocked(sm.A, sm.dinv, sm.P[0], tid);

    // ---- q_cov = X^T X with block-triangular k skipping ----
    float acc[8][8];
#pragma unroll
    for (int a = 0; a < 8; a++)
#pragma unroll
        for (int b = 0; b < 8; b++) acc[a][b] = 0.0f;
#pragma unroll
    for (int kb = 0; kb < 8; kb++) {
        for (int kk = 0; kk < 16; kk++) {
            const float* Ak = sm.A + (kb*16 + kk)*PAD;
            float xi[8], xj[8];
#pragma unroll
            for (int a = 0; a <= kb; a++) {
                xi[a] = Ak[ty + 16*a];
                xj[a] = Ak[tx + 16*a];
            }
#pragma unroll
            for (int a = 0; a <= kb; a++)
#pragma unroll
                for (int b = 0; b <= a; b++)
                    acc[a][b] += xi[a] * xj[b];
        }
    }
    __syncthreads();
#pragma unroll
    for (int a = 0; a < 8; a++)
#pragma unroll
        for (int b = 0; b <= a; b++) {
            int i = ty + 16*a, j = tx + 16*b;
            sm.A[i*PAD + j] = acc[a][b];
            if (b < a) sm.A[j*PAD + i] = acc[a][b];
        }
    __syncthreads();

    // ---- q_mu = q_cov @ utlv ----
    if (tid < DD) {
        float a = 0.0f;
#pragma unroll 8
        for (int e = 0; e < DD; e++) a += sm.A[tid*PAD + e] * sm.utlv[e];
        sm.qmu[tid] = a;
    }
    __syncthreads();

    if (tid < DD) sm.red[tid] = sm.A[tid*PAD + tid] + sm.qmu[tid]*sm.qmu[tid];
    __syncthreads();
    float trmu = 0.0f;
    if (tid < 32) {
        float p = sm.red[tid] + sm.red[tid+32] + sm.red[tid+64] + sm.red[tid+96];
#pragma unroll
        for (int off = 16; off > 0; off >>= 1)
            p += __shfl_xor_sync(0xFFFFFFFFu, p, off);
        trmu = p;
    }

    // ---- Lcov = chol(q_cov) ----
    chol_blocked(sm.A, sm.dinv, tid);

    if (tid < DD) sm.red[tid] = logf(sm.A[tid*PAD + tid]);
    __syncthreads();

    // ---- w = q_mu + Lcov @ eps ; KL ----
    if (tid < DD) {
        float a = sm.qmu[tid];
        for (int e = 0; e <= tid; e++)
            a += sm.A[tid*PAD + e] * sm.epsv[e];
        g_w[(s*OO + o)*DD + tid] = a;
    }
    if (tid < 32) {
        float p = sm.red[tid] + sm.red[tid+32] + sm.red[tid+64] + sm.red[tid+96];
#pragma unroll
        for (int off = 16; off > 0; off >>= 1)
            p += __shfl_xor_sync(0xFFFFFFFFu, p, off);
        if (tid == 0)
            g_klso[so] = 0.5f * (trmu - (float)DD) - p;
    }
}

// ---- k2: F_out / U_out GEMMs, float4-over-k ----
#define KP 36
__global__ __launch_bounds__(256, 2)
void k2_gemm(const float* __restrict__ F, const float* __restrict__ U,
             float* __restrict__ outF, float* __restrict__ outU) {
    __shared__ float At[128*KP];
    __shared__ float Bt[128*KP];
    const int b = blockIdx.x;
    const int tid = threadIdx.x;
    const int ty = tid >> 4, tx = tid & 15;

    int s;
    const float* Ag;
    float* Cg;
    if (b < SS * (NN/128)) {
        s = b >> 5;
        int nt = b & 31;
        Ag = F + (size_t)(s*NN + nt*128) * DD;
        Cg = outF + (size_t)(s*NN + nt*128) * OO;
    } else {
        s = b - SS * (NN/128);
        Ag = U + (size_t)(s*MM) * DD;
        Cg = outU + (size_t)(s*MM) * OO;
    }
    const float* W = g_w + (size_t)s * OO * DD;

    float acc[8][8];
#pragma unroll
    for (int a = 0; a < 8; a++)
#pragma unroll
        for (int c = 0; c < 8; c++) acc[a][c] = 0.0f;

    for (int kb = 0; kb < DD; kb += 32) {
        __syncthreads();
        for (int idx = tid; idx < 128*8; idx += 256) {
            int r = idx >> 3, c4 = idx & 7;
            float4 v = *(const float4*)&Ag[r*DD + kb + 4*c4];
            v.x = fmaxf(v.x, 0.f); v.y = fmaxf(v.y, 0.f);
            v.z = fmaxf(v.z, 0.f); v.w = fmaxf(v.w, 0.f);
            *(float4*)&At[r*KP + 4*c4] = v;
            *(float4*)&Bt[r*KP + 4*c4] = *(const float4*)&W[r*DD + kb + 4*c4];
        }
        __syncthreads();
#pragma unroll
        for (int k4 = 0; k4 < 8; k4++) {
            float4 bv[8];
#pragma unroll
            for (int c = 0; c < 8; c++)
                bv[c] = *(const float4*)&Bt[(tx + 16*c)*KP + 4*k4];
#pragma unroll
            for (int a = 0; a < 8; a++) {
                float4 av = *(const float4*)&At[(ty + 16*a)*KP + 4*k4];
#pragma unroll
                for (int c = 0; c < 8; c++) {
                    acc[a][c] += av.x * bv[c].x;
                    acc[a][c] += av.y * bv[c].y;
                    acc[a][c] += av.z * bv[c].z;
                    acc[a][c] += av.w * bv[c].w;
                }
            }
        }
    }
#pragma unroll
    for (int a = 0; a < 8; a++)
#pragma unroll
        for (int c = 0; c < 8; c++)
            Cg[(ty + 16*a)*OO + tx + 16*c] = acc[a][c];
}

__global__ void k3_kl(float* __restrict__ kl) {
    int s = threadIdx.x;
    if (s < SS) {
        float a = 0.0f;
        for (int o = 0; o < OO; o++) a += g_klso[s*OO + o];
        kl[s] = a;
    }
}

extern "C" void kernel_launch(void* const* d_in, const int* in_sizes, int n_in,
                              void* d_out, int out_size) {
    const float* F        = (const float*)d_in[0];
    const float* U        = (const float*)d_in[1];
    const float* pmu      = (const float*)d_in[2];
    const float* plogprec = (const float*)d_in[3];
    const float* eps      = (const float*)d_in[4];

    float* out  = (float*)d_out;
    float* outF = out;
    float* outU = outF + (size_t)SS*NN*OO;
    float* outK = outU + (size_t)SS*MM*OO;

    cudaFuncSetAttribute(k1_factor, cudaFuncAttributeMaxDynamicSharedMemorySize,
                         (int)sizeof(K1Smem));

    k1_factor<<<SS*OO, 256, sizeof(K1Smem)>>>(U, pmu, plogprec, eps);
    k2_gemm<<<SS*(NN/128) + SS, 256>>>(F, U, outF, outU);
    k3_kl<<<1, 32>>>(outK);
}